// round 4
// baseline (speedup 1.0000x reference)
#include <cuda_runtime.h>

#define CIN     512
#define COUT    32
#define HW      56
#define PLANE   3136
#define HPAD    58
#define WPAD    64
#define CHPAD   (HPAD * WPAD)        // 3712 floats per padded channel
#define KC      8
#define NCHUNK  (CIN / KC)           // 64
#define TH      8
#define TW      28
#define XROWS   10
#define XCOLS   32
#define NTHREADS 224
#define XELEMS  (KC * XROWS * XCOLS) // 2560 floats
#define WELEMS  (KC * 9 * COUT)      // 2304 floats
#define XF4     (XELEMS / 4)         // 640 16B ops
#define WF4     (WELEMS / 4)         // 576 16B ops

// scratch (device globals per harness rules)
__device__ float g_xpad[32 * CIN * CHPAD];       // BN+ReLU'd, zero-padded halo
__device__ float g_wt[CIN * 9 * COUT];           // weights as [c][kh][kw][oc]

// ---------------- Kernel 1: BN+ReLU into padded layout ----------------
__global__ __launch_bounds__(256) void bn_relu_pad(
    const float* __restrict__ x, const float* __restrict__ gamma,
    const float* __restrict__ beta, const float* __restrict__ rmean,
    const float* __restrict__ rvar)
{
    __shared__ float sp[PLANE];
    const int id  = blockIdx.x;          // plane id = n*512 + c
    const int c   = id & (CIN - 1);
    const int tid = threadIdx.x;

    float inv = rsqrtf(__ldg(&rvar[c]) + 1e-5f);
    float sc  = __ldg(&gamma[c]) * inv;
    float sh  = fmaf(-__ldg(&rmean[c]), sc, __ldg(&beta[c]));

    const float4* src = (const float4*)(x + (size_t)id * PLANE);
    for (int i = tid; i < PLANE / 4; i += 256) {
        float4 v = src[i];
        v.x = fmaxf(fmaf(v.x, sc, sh), 0.0f);
        v.y = fmaxf(fmaf(v.y, sc, sh), 0.0f);
        v.z = fmaxf(fmaf(v.z, sc, sh), 0.0f);
        v.w = fmaxf(fmaf(v.w, sc, sh), 0.0f);
        ((float4*)sp)[i] = v;
    }
    __syncthreads();

    float4* dst = (float4*)(g_xpad + (size_t)id * CHPAD);
    for (int i = tid; i < HPAD * (WPAD / 4); i += 256) {
        int hp = i >> 4, v4 = i & 15;
        float4 o = make_float4(0.f, 0.f, 0.f, 0.f);
        if (hp >= 1 && hp <= HW) {
            const float* row = sp + (hp - 1) * HW;
            int pc = v4 * 4;
            float t[4];
#pragma unroll
            for (int j = 0; j < 4; j++) {
                int p = pc + j;
                t[j] = (p >= 1 && p <= HW) ? row[p - 1] : 0.0f;
            }
            o = make_float4(t[0], t[1], t[2], t[3]);
        }
        dst[i] = o;
    }
}

// ---------------- Kernel 2: weight transpose [oc][c][k] -> [c][k][oc] ----------------
__global__ __launch_bounds__(256) void wt_transpose(const float* __restrict__ cw)
{
    int idx = blockIdx.x * 256 + threadIdx.x;
    if (idx >= CIN * 9 * COUT) return;
    int ck = idx >> 5, oc = idx & 31;
    g_wt[idx] = cw[oc * (CIN * 9) + ck];
}

// ---------------- Kernel 3: conv 3x3, 16B cp.async double-buffered, FFMA2 ----------------
__device__ __forceinline__ unsigned smem_u32(const void* p) {
    return (unsigned)__cvta_generic_to_shared(p);
}

__global__ __launch_bounds__(NTHREADS, 4)
void conv3x3_async(float* __restrict__ out)
{
    __shared__ __align__(16) float s_x[2][XELEMS];   // 20.5 KB
    __shared__ __align__(16) float s_w[2][WELEMS];   // 18.4 KB

    const int tid = threadIdx.x;
    const int n   = blockIdx.z;
    const int h0  = blockIdx.y * TH;
    const int w0  = blockIdx.x * TW;

    const int ocg = tid & 3;           // quads share x float4 (LDS broadcast)
    const int pix = tid >> 2;
    const int ty  = pix / 7;
    const int tx4 = (pix % 7) * 4;

    // chunk-invariant staging offsets (3 slots, float units / byte units)
    unsigned xsrc[3], xdst[3];
#pragma unroll
    for (int t = 0; t < 3; t++) {
        int s = tid + t * NTHREADS;            // < XF4 except slot2 when tid>=192
        int c = s / 80, rem = s % 80;
        int r = rem / 8, v = rem % 8;
        xsrc[t] = c * CHPAD + (h0 + r) * WPAD + w0 + v * 4;
        xdst[t] = ((c * XROWS + r) * XCOLS + v * 4) * 4u;
    }

    const float* xplane = g_xpad + (size_t)n * CIN * CHPAD;
    unsigned sxb[2] = { smem_u32(s_x[0]), smem_u32(s_x[1]) };
    unsigned swb[2] = { smem_u32(s_w[0]), smem_u32(s_w[1]) };

    unsigned long long acc[4][4];
#pragma unroll
    for (int j = 0; j < 4; j++)
#pragma unroll
        for (int q = 0; q < 4; q++) acc[j][q] = 0ull;

    // ---- staging lambda ----
    auto stage = [&](int k, int b) {
        const float* xb = xplane + (size_t)k * KC * CHPAD;
        const float* wb = g_wt + k * WELEMS;
#pragma unroll
        for (int t = 0; t < 3; t++) {
            if (t < 2 || tid < XF4 - 2 * NTHREADS) {
                asm volatile("cp.async.cg.shared.global [%0], [%1], 16;\n"
                             :: "r"(sxb[b] + xdst[t]), "l"(xb + xsrc[t]));
            }
        }
#pragma unroll
        for (int t = 0; t < 3; t++) {
            int s = tid + t * NTHREADS;
            if (t < 2 || tid < WF4 - 2 * NTHREADS) {
                asm volatile("cp.async.cg.shared.global [%0], [%1], 16;\n"
                             :: "r"(swb[b] + (unsigned)s * 16u), "l"(wb + s * 4));
            }
        }
        asm volatile("cp.async.commit_group;\n" ::: "memory");
    };

    stage(0, 0);
    stage(1, 1);

#pragma unroll 1
    for (int k = 0; k < NCHUNK; k++) {
        if (k < NCHUNK - 1) asm volatile("cp.async.wait_group 1;\n" ::: "memory");
        else                asm volatile("cp.async.wait_group 0;\n" ::: "memory");
        __syncthreads();
        const int b = k & 1;
        const float* sx = s_x[b];
        const float* sw = s_w[b];
#pragma unroll
        for (int c = 0; c < KC; c++) {
#pragma unroll
            for (int kh = 0; kh < 3; kh++) {
                const float* xr = sx + ((c * XROWS + ty + kh) * XCOLS + tx4);
                float4 a  = *(const float4*)xr;
                float2 b2 = *(const float2*)(xr + 4);
                float xv[6] = {a.x, a.y, a.z, a.w, b2.x, b2.y};
                unsigned long long xx[6];
#pragma unroll
                for (int t = 0; t < 6; t++) {
                    unsigned u = __float_as_uint(xv[t]);
                    asm("mov.b64 %0, {%1, %1};" : "=l"(xx[t]) : "r"(u));
                }
#pragma unroll
                for (int kw = 0; kw < 3; kw++) {
                    const unsigned long long* wp = (const unsigned long long*)
                        (sw + ((c * 3 + kh) * 3 + kw) * COUT + ocg * 8);
                    unsigned long long wv0 = wp[0], wv1 = wp[1], wv2 = wp[2], wv3 = wp[3];
#pragma unroll
                    for (int q = 0; q < 4; q++) {
                        asm("fma.rn.f32x2 %0, %1, %2, %0;" : "+l"(acc[0][q]) : "l"(xx[kw + q]), "l"(wv0));
                        asm("fma.rn.f32x2 %0, %1, %2, %0;" : "+l"(acc[1][q]) : "l"(xx[kw + q]), "l"(wv1));
                        asm("fma.rn.f32x2 %0, %1, %2, %0;" : "+l"(acc[2][q]) : "l"(xx[kw + q]), "l"(wv2));
                        asm("fma.rn.f32x2 %0, %1, %2, %0;" : "+l"(acc[3][q]) : "l"(xx[kw + q]), "l"(wv3));
                    }
                }
            }
        }
        __syncthreads();
        if (k + 2 < NCHUNK) stage(k + 2, b);
    }

    // ---- epilogue ----
    const int h = h0 + ty;
#pragma unroll
    for (int j = 0; j < 4; j++) {
        int oc0 = ocg * 8 + 2 * j;
        float* o0 = out + ((size_t)(n * COUT + oc0) * PLANE) + h * HW + w0 + tx4;
        float* o1 = o0 + PLANE;
#pragma unroll
        for (int q = 0; q < 4; q++) {
            unsigned lo, hi;
            asm("mov.b64 {%0, %1}, %2;" : "=r"(lo), "=r"(hi) : "l"(acc[j][q]));
            o0[q] = __uint_as_float(lo);
            o1[q] = __uint_as_float(hi);
        }
    }
}

extern "C" void kernel_launch(void* const* d_in, const int* in_sizes, int n_in,
                              void* d_out, int out_size) {
    // inputs: x_slice, out_map(unused), bn_weight, bn_bias, running_mean,
    //         running_var, conv_weight, write_offset(unused)
    const float* x     = (const float*)d_in[0];
    const float* gamma = (const float*)d_in[2];
    const float* beta  = (const float*)d_in[3];
    const float* rmean = (const float*)d_in[4];
    const float* rvar  = (const float*)d_in[5];
    const float* cw    = (const float*)d_in[6];
    float* out = (float*)d_out;

    bn_relu_pad<<<32 * CIN, 256>>>(x, gamma, beta, rmean, rvar);
    wt_transpose<<<(CIN * 9 * COUT + 255) / 256, 256>>>(cw);

    dim3 grid(HW / TW, HW / TH, 32);   // (2, 7, 32) = 448 CTAs
    conv3x3_async<<<grid, NTHREADS>>>(out);
}

// round 5
// speedup vs baseline: 1.0062x; 1.0062x over previous
#include <cuda_runtime.h>

#define CIN     512
#define COUT    32
#define HW      56
#define PLANE   3136
#define HPAD    58
#define WPAD    64
#define CHPAD   (HPAD * WPAD)        // 3712 floats per padded channel
#define KC      8
#define NCHUNK  (CIN / KC)           // 64
#define TH      8
#define TW      28
#define XROWS   10
#define XCOLS   32
#define NTHREADS 224
#define XELEMS  (KC * XROWS * XCOLS) // 2560 floats
#define WELEMS  (KC * 9 * COUT)      // 2304 floats
#define XF4     (XELEMS / 4)         // 640 16B ops
#define WF4     (WELEMS / 4)         // 576 16B ops

// scratch (device globals per harness rules)
__device__ float g_xpad[32 * CIN * CHPAD];       // BN+ReLU'd, zero-padded halo
__device__ float g_wt[CIN * 9 * COUT];           // weights as [c][kh][kw][oc]

// ---------------- Kernel 1: BN+ReLU into padded layout ----------------
__global__ __launch_bounds__(256) void bn_relu_pad(
    const float* __restrict__ x, const float* __restrict__ gamma,
    const float* __restrict__ beta, const float* __restrict__ rmean,
    const float* __restrict__ rvar)
{
    __shared__ float sp[PLANE];
    const int id  = blockIdx.x;          // plane id = n*512 + c
    const int c   = id & (CIN - 1);
    const int tid = threadIdx.x;

    float inv = rsqrtf(__ldg(&rvar[c]) + 1e-5f);
    float sc  = __ldg(&gamma[c]) * inv;
    float sh  = fmaf(-__ldg(&rmean[c]), sc, __ldg(&beta[c]));

    const float4* src = (const float4*)(x + (size_t)id * PLANE);
    for (int i = tid; i < PLANE / 4; i += 256) {
        float4 v = src[i];
        v.x = fmaxf(fmaf(v.x, sc, sh), 0.0f);
        v.y = fmaxf(fmaf(v.y, sc, sh), 0.0f);
        v.z = fmaxf(fmaf(v.z, sc, sh), 0.0f);
        v.w = fmaxf(fmaf(v.w, sc, sh), 0.0f);
        ((float4*)sp)[i] = v;
    }
    __syncthreads();

    float4* dst = (float4*)(g_xpad + (size_t)id * CHPAD);
    for (int i = tid; i < HPAD * (WPAD / 4); i += 256) {
        int hp = i >> 4, v4 = i & 15;
        float4 o = make_float4(0.f, 0.f, 0.f, 0.f);
        if (hp >= 1 && hp <= HW) {
            const float* row = sp + (hp - 1) * HW;
            int pc = v4 * 4;
            float t[4];
#pragma unroll
            for (int j = 0; j < 4; j++) {
                int p = pc + j;
                t[j] = (p >= 1 && p <= HW) ? row[p - 1] : 0.0f;
            }
            o = make_float4(t[0], t[1], t[2], t[3]);
        }
        dst[i] = o;
    }
}

// ---------------- Kernel 2: weight transpose [oc][c][k] -> [c][k][oc] ----------------
__global__ __launch_bounds__(256) void wt_transpose(const float* __restrict__ cw)
{
    int idx = blockIdx.x * 256 + threadIdx.x;
    if (idx >= CIN * 9 * COUT) return;
    int ck = idx >> 5, oc = idx & 31;
    g_wt[idx] = cw[oc * (CIN * 9) + ck];
}

// ---------------- Kernel 3: conv 3x3, 16B cp.async double-buffered, FFMA2 ----------------
__device__ __forceinline__ unsigned smem_u32(const void* p) {
    return (unsigned)__cvta_generic_to_shared(p);
}

__global__ __launch_bounds__(NTHREADS, 4)
void conv3x3_async(float* __restrict__ out)
{
    __shared__ __align__(16) float s_x[2][XELEMS];   // 20.5 KB
    __shared__ __align__(16) float s_w[2][WELEMS];   // 18.4 KB

    const int tid = threadIdx.x;
    const int n   = blockIdx.z;
    const int h0  = blockIdx.y * TH;
    const int w0  = blockIdx.x * TW;

    const int ocg = tid & 3;           // quads share x float4 (LDS broadcast)
    const int pix = tid >> 2;
    const int ty  = pix / 7;
    const int tx4 = (pix % 7) * 4;

    // chunk-invariant staging offsets (3 slots, float units / byte units)
    unsigned xsrc[3], xdst[3];
#pragma unroll
    for (int t = 0; t < 3; t++) {
        int s = tid + t * NTHREADS;            // < XF4 except slot2 when tid>=192
        int c = s / 80, rem = s % 80;
        int r = rem / 8, v = rem % 8;
        xsrc[t] = c * CHPAD + (h0 + r) * WPAD + w0 + v * 4;
        xdst[t] = ((c * XROWS + r) * XCOLS + v * 4) * 4u;
    }

    const float* xplane = g_xpad + (size_t)n * CIN * CHPAD;
    unsigned sxb[2] = { smem_u32(s_x[0]), smem_u32(s_x[1]) };
    unsigned swb[2] = { smem_u32(s_w[0]), smem_u32(s_w[1]) };

    unsigned long long acc[4][4];
#pragma unroll
    for (int j = 0; j < 4; j++)
#pragma unroll
        for (int q = 0; q < 4; q++) acc[j][q] = 0ull;

    // ---- staging lambda ----
    auto stage = [&](int k, int b) {
        const float* xb = xplane + (size_t)k * KC * CHPAD;
        const float* wb = g_wt + k * WELEMS;
#pragma unroll
        for (int t = 0; t < 3; t++) {
            if (t < 2 || tid < XF4 - 2 * NTHREADS) {
                asm volatile("cp.async.cg.shared.global [%0], [%1], 16;\n"
                             :: "r"(sxb[b] + xdst[t]), "l"(xb + xsrc[t]));
            }
        }
#pragma unroll
        for (int t = 0; t < 3; t++) {
            int s = tid + t * NTHREADS;
            if (t < 2 || tid < WF4 - 2 * NTHREADS) {
                asm volatile("cp.async.cg.shared.global [%0], [%1], 16;\n"
                             :: "r"(swb[b] + (unsigned)s * 16u), "l"(wb + s * 4));
            }
        }
        asm volatile("cp.async.commit_group;\n" ::: "memory");
    };

    stage(0, 0);
    stage(1, 1);

#pragma unroll 1
    for (int k = 0; k < NCHUNK; k++) {
        if (k < NCHUNK - 1) asm volatile("cp.async.wait_group 1;\n" ::: "memory");
        else                asm volatile("cp.async.wait_group 0;\n" ::: "memory");
        __syncthreads();
        const int b = k & 1;
        const float* sx = s_x[b];
        const float* sw = s_w[b];
#pragma unroll
        for (int c = 0; c < KC; c++) {
#pragma unroll
            for (int kh = 0; kh < 3; kh++) {
                const float* xr = sx + ((c * XROWS + ty + kh) * XCOLS + tx4);
                float4 a  = *(const float4*)xr;
                float2 b2 = *(const float2*)(xr + 4);
                float xv[6] = {a.x, a.y, a.z, a.w, b2.x, b2.y};
                unsigned long long xx[6];
#pragma unroll
                for (int t = 0; t < 6; t++) {
                    unsigned u = __float_as_uint(xv[t]);
                    asm("mov.b64 %0, {%1, %1};" : "=l"(xx[t]) : "r"(u));
                }
#pragma unroll
                for (int kw = 0; kw < 3; kw++) {
                    const unsigned long long* wp = (const unsigned long long*)
                        (sw + ((c * 3 + kh) * 3 + kw) * COUT + ocg * 8);
                    unsigned long long wv0 = wp[0], wv1 = wp[1], wv2 = wp[2], wv3 = wp[3];
#pragma unroll
                    for (int q = 0; q < 4; q++) {
                        asm("fma.rn.f32x2 %0, %1, %2, %0;" : "+l"(acc[0][q]) : "l"(xx[kw + q]), "l"(wv0));
                        asm("fma.rn.f32x2 %0, %1, %2, %0;" : "+l"(acc[1][q]) : "l"(xx[kw + q]), "l"(wv1));
                        asm("fma.rn.f32x2 %0, %1, %2, %0;" : "+l"(acc[2][q]) : "l"(xx[kw + q]), "l"(wv2));
                        asm("fma.rn.f32x2 %0, %1, %2, %0;" : "+l"(acc[3][q]) : "l"(xx[kw + q]), "l"(wv3));
                    }
                }
            }
        }
        __syncthreads();
        if (k + 2 < NCHUNK) stage(k + 2, b);
    }

    // ---- epilogue ----
    const int h = h0 + ty;
#pragma unroll
    for (int j = 0; j < 4; j++) {
        int oc0 = ocg * 8 + 2 * j;
        float* o0 = out + ((size_t)(n * COUT + oc0) * PLANE) + h * HW + w0 + tx4;
        float* o1 = o0 + PLANE;
#pragma unroll
        for (int q = 0; q < 4; q++) {
            unsigned lo, hi;
            asm("mov.b64 {%0, %1}, %2;" : "=r"(lo), "=r"(hi) : "l"(acc[j][q]));
            o0[q] = __uint_as_float(lo);
            o1[q] = __uint_as_float(hi);
        }
    }
}

extern "C" void kernel_launch(void* const* d_in, const int* in_sizes, int n_in,
                              void* d_out, int out_size) {
    // inputs: x_slice, out_map(unused), bn_weight, bn_bias, running_mean,
    //         running_var, conv_weight, write_offset(unused)
    const float* x     = (const float*)d_in[0];
    const float* gamma = (const float*)d_in[2];
    const float* beta  = (const float*)d_in[3];
    const float* rmean = (const float*)d_in[4];
    const float* rvar  = (const float*)d_in[5];
    const float* cw    = (const float*)d_in[6];
    float* out = (float*)d_out;

    bn_relu_pad<<<32 * CIN, 256>>>(x, gamma, beta, rmean, rvar);
    wt_transpose<<<(CIN * 9 * COUT + 255) / 256, 256>>>(cw);

    dim3 grid(HW / TW, HW / TH, 32);   // (2, 7, 32) = 448 CTAs
    conv3x3_async<<<grid, NTHREADS>>>(out);
}